// round 6
// baseline (speedup 1.0000x reference)
#include <cuda_runtime.h>
#include <math.h>
#include <stdint.h>

#define Bb 8
#define Ll 39
#define Dd 256
#define DE 65536            // D*D
#define Mm 252
#define Ff 63504            // M*M
#define BL 312              // B*L
#define OUT_O 79872         // B*L*D

// ---- scratch (device globals; no allocation allowed) ----
__device__ float g_scores[BL * Ll];              // 12168
__device__ float g_sumsq[BL];                    // 312
__device__ float g_out_acc[OUT_O];               // 79872
__device__ float g_x[(size_t)Bb * Ll * DE];      // 81.8 MB  post-attention maps
__device__ float g_e[(size_t)BL * Ff];           // 79.3 MB  tril(exp(conv)) rows

// ===========================================================================
// packed fp32x2 helpers (FFMA2 — compiles on sm_103 per round-5 ptxas log)
// ===========================================================================
__device__ __forceinline__ unsigned long long pk2(float lo, float hi) {
    unsigned long long r;
    asm("mov.b64 %0, {%1, %2};" : "=l"(r) : "f"(lo), "f"(hi));
    return r;
}
__device__ __forceinline__ void ffma2(unsigned long long& d, unsigned long long a, unsigned long long b) {
    asm("fma.rn.f32x2 %0, %1, %2, %0;" : "+l"(d) : "l"(a), "l"(b));
}
__device__ __forceinline__ float2 unpk(unsigned long long v) {
    float2 r;
    asm("mov.b64 {%0, %1}, %2;" : "=f"(r.x), "=f"(r.y) : "l"(v));
    return r;
}

// ---------------------------------------------------------------------------
// init: zero accumulators
// ---------------------------------------------------------------------------
__global__ void init_kernel() {
    int i = blockIdx.x * 256 + threadIdx.x;
    if (i < BL * Ll) g_scores[i] = 0.f;
    if (i < BL)      g_sumsq[i] = 0.f;
    if (i < OUT_O)   g_out_acc[i] = 0.f;
}

// ---------------------------------------------------------------------------
// K1: Gram matrix  scores[b,i,j] = dot(H[b,i], H[b,j]) / 256
// ---------------------------------------------------------------------------
__global__ __launch_bounds__(256) void gram_kernel(const float* __restrict__ H) {
    __shared__ float sh[Ll * 257];
    int b = blockIdx.y, ch = blockIdx.x;
    int t = threadIdx.x;
    const float* Hb = H + (size_t)b * Ll * DE + ch * 256;
    for (int idx = t; idx < Ll * 256; idx += 256) {
        int i = idx >> 8, c = idx & 255;
        sh[i * 257 + c] = Hb[(size_t)i * DE + c];
    }
    __syncthreads();
    int a = t >> 4, bb = t & 15;
    float acc[3][3] = {};
    for (int k = 0; k < 256; k++) {
        float ra[3], rb[3];
#pragma unroll
        for (int p = 0; p < 3; p++) { int i = a + 16 * p; ra[p] = sh[min(i, Ll - 1) * 257 + k]; }
#pragma unroll
        for (int q = 0; q < 3; q++) { int j = bb + 16 * q; rb[q] = sh[min(j, Ll - 1) * 257 + k]; }
#pragma unroll
        for (int p = 0; p < 3; p++)
#pragma unroll
            for (int q = 0; q < 3; q++) acc[p][q] += ra[p] * rb[q];
    }
#pragma unroll
    for (int p = 0; p < 3; p++)
#pragma unroll
        for (int q = 0; q < 3; q++) {
            int i = a + 16 * p, j = bb + 16 * q;
            if (i < Ll && j < Ll)
                atomicAdd(&g_scores[(b * Ll + i) * Ll + j], acc[p][q] * (1.f / 256.f));
        }
}

// ---------------------------------------------------------------------------
// K2: softmax over j (39)
// ---------------------------------------------------------------------------
__global__ void softmax_kernel(float* __restrict__ attn) {
    int row = blockIdx.x;
    int lane = threadIdx.x;
    float v0 = (lane < Ll) ? g_scores[row * Ll + lane] : -1e30f;
    float v1 = (lane + 32 < Ll) ? g_scores[row * Ll + lane + 32] : -1e30f;
    float m = fmaxf(v0, v1);
#pragma unroll
    for (int off = 16; off; off >>= 1) m = fmaxf(m, __shfl_xor_sync(0xffffffffu, m, off));
    float e0 = (lane < Ll) ? expf(v0 - m) : 0.f;
    float e1 = (lane + 32 < Ll) ? expf(v1 - m) : 0.f;
    float s = e0 + e1;
#pragma unroll
    for (int off = 16; off; off >>= 1) s += __shfl_xor_sync(0xffffffffu, s, off);
    float inv = 1.f / s;
    if (lane < Ll) attn[row * Ll + lane] = e0 * inv;
    if (lane + 32 < Ll) attn[row * Ll + lane + 32] = e1 * inv;
}

// ---------------------------------------------------------------------------
// K3: attn apply — float2 per thread, FFMA2, attn duplicated in smem
// grid (128, 8), block 256
// ---------------------------------------------------------------------------
__global__ __launch_bounds__(256) void attnapply_kernel(const float* __restrict__ H,
                                                        const float* __restrict__ attn) {
    int b = blockIdx.y;
    int p2 = blockIdx.x * 256 + threadIdx.x;       // float2 index, 0..32767
    __shared__ float2 sA[Ll * Ll];
    for (int idx = threadIdx.x; idx < Ll * Ll; idx += 256) {
        float s = attn[b * Ll * Ll + idx];
        sA[idx] = make_float2(s, s);
    }
    __syncthreads();
    unsigned long long acc[Ll];
#pragma unroll
    for (int i = 0; i < Ll; i++) acc[i] = 0ull;
    const unsigned long long* Hb = (const unsigned long long*)(H + (size_t)b * Ll * DE) + p2;
    const unsigned long long* sAu = (const unsigned long long*)sA;
#pragma unroll 1
    for (int j = 0; j < Ll; j++) {
        unsigned long long h = Hb[(size_t)j * (DE / 2)];
#pragma unroll
        for (int i = 0; i < Ll; i++) ffma2(acc[i], h, sAu[i * Ll + j]);
    }
    unsigned long long* xb = (unsigned long long*)(g_x + (size_t)b * Ll * DE) + p2;
#pragma unroll
    for (int i = 0; i < Ll; i++) xb[(size_t)i * (DE / 2)] = acc[i];
}

// ---------------------------------------------------------------------------
// K4: conv 5x5 (39->39 ch, VALID) fused +bias, exp, sumsq, tril — FFMA2
// grid (4,4,312), block 256 (16x16), 4x4 outputs/thread (as 4x2 f32x2)
// ---------------------------------------------------------------------------
__global__ __launch_bounds__(256, 2) void conv_kernel(const float* __restrict__ W,
                                                      const float* __restrict__ bias) {
    int bo = blockIdx.z;
    int b = bo / Ll, o = bo % Ll;
    int base_r = blockIdx.y * 64, base_c = blockIdx.x * 64;
    __shared__ float s_in[68 * 72];
    __shared__ float2 s_w2[Ll * 25];
    __shared__ float ws[8];
    int t = threadIdx.x;
    for (int idx = t; idx < Ll * 25; idx += 256) {
        float w = W[o * (Ll * 25) + idx];
        s_w2[idx] = make_float2(w, w);
    }
    const float* xb = g_x + (size_t)b * Ll * DE;
    int ty = t >> 4, tx = t & 15;
    int r0 = ty * 4, c0 = tx * 4;
    unsigned long long accp[4][2];
#pragma unroll
    for (int i = 0; i < 4; i++) { accp[i][0] = 0ull; accp[i][1] = 0ull; }
    const unsigned long long* s_wu = (const unsigned long long*)s_w2;
    for (int c = 0; c < Ll; c++) {
        __syncthreads();
        for (int idx = t; idx < 68 * 68; idx += 256) {
            int rr = idx / 68, cc = idx % 68;
            int gr = base_r + rr, gc = base_c + cc;
            float v = 0.f;
            if (gr < Dd && gc < Dd) v = xb[(size_t)c * DE + gr * Dd + gc];
            s_in[rr * 72 + cc] = v;
        }
        __syncthreads();
        float r[8][8];
#pragma unroll
        for (int i = 0; i < 8; i++) {
            float4 v0 = *(const float4*)&s_in[(r0 + i) * 72 + c0];
            float4 v1 = *(const float4*)&s_in[(r0 + i) * 72 + c0 + 4];
            r[i][0] = v0.x; r[i][1] = v0.y; r[i][2] = v0.z; r[i][3] = v0.w;
            r[i][4] = v1.x; r[i][5] = v1.y; r[i][6] = v1.z; r[i][7] = v1.w;
        }
        const unsigned long long* wc = s_wu + c * 25;
#pragma unroll
        for (int kh = 0; kh < 5; kh++)
#pragma unroll
            for (int kw = 0; kw < 5; kw++) {
                unsigned long long wp = wc[kh * 5 + kw];
#pragma unroll
                for (int i = 0; i < 4; i++) {
                    ffma2(accp[i][0], pk2(r[i + kh][kw], r[i + kh][kw + 1]), wp);
                    ffma2(accp[i][1], pk2(r[i + kh][kw + 2], r[i + kh][kw + 3]), wp);
                }
            }
    }
    // epilogue: +bias, exp, sumsq (full matrix), tril store
    float bv = bias[o];
    float bsum = 0.f;
    size_t ebase = (size_t)bo * Ff;
#pragma unroll
    for (int i = 0; i < 4; i++) {
        float2 lo = unpk(accp[i][0]);
        float2 hi = unpk(accp[i][1]);
        float vals[4] = { lo.x, lo.y, hi.x, hi.y };
#pragma unroll
        for (int j = 0; j < 4; j++) {
            int R = base_r + r0 + i, C = base_c + c0 + j;
            if (R < Mm && C < Mm) {
                float e = expf(vals[j] + bv);
                bsum += e * e;
                g_e[ebase + (size_t)R * Mm + C] = (R >= C) ? e : 0.f;
            }
        }
    }
#pragma unroll
    for (int off = 16; off; off >>= 1) bsum += __shfl_down_sync(0xffffffffu, bsum, off);
    if ((t & 31) == 0) ws[t >> 5] = bsum;
    __syncthreads();
    if (t == 0) {
        float tot = 0.f;
#pragma unroll
        for (int w = 0; w < 8; w++) tot += ws[w];
        atomicAdd(&g_sumsq[bo], tot);
    }
}

// ---------------------------------------------------------------------------
// K5: SIMT GEMM with FFMA2.  Out[312,256] += E[312,63504] @ W2^T.
// 64x64 tiles, split-K=16 (chunk 3969), block 256, 4x4 micro-tile
// (2x f32x2 per row), atomicAdd accumulate.
// ---------------------------------------------------------------------------
#define KCH 3969
__global__ __launch_bounds__(256) void gemm_kernel(const float* __restrict__ W2) {
    __shared__ float sA[16 * 68];
    __shared__ float sB[16 * 68];
    int n0 = blockIdx.x * 64, m0 = blockIdx.y * 64;
    int k0 = blockIdx.z * KCH, kend = k0 + KCH;   // 16*3969 == 63504 exactly
    int t = threadIdx.x;
    int mt = 4 * (t >> 4), nt = 4 * (t & 15);
    unsigned long long acc[4][2];
#pragma unroll
    for (int i = 0; i < 4; i++) { acc[i][0] = 0ull; acc[i][1] = 0ull; }
    for (int kb = k0; kb < kend; kb += 16) {
        __syncthreads();
#pragma unroll
        for (int p = 0; p < 4; p++) {
            int idx = t + p * 256;
            int rl = idx >> 4, kl = idx & 15;
            int kk = kb + kl;
            int m = m0 + rl;
            float av = (m < BL && kk < kend) ? g_e[(size_t)m * Ff + kk] : 0.f;
            sA[kl * 68 + rl] = av;
            int n = n0 + rl;
            float bvv = (kk < kend) ? W2[(size_t)n * Ff + kk] : 0.f;
            sB[kl * 68 + rl] = bvv;
        }
        __syncthreads();
#pragma unroll
        for (int kk = 0; kk < 16; kk++) {
            float4 a = *(const float4*)&sA[kk * 68 + mt];
            // B pairs: contiguous n, 8-byte aligned (nt multiple of 4)
            unsigned long long b0 = *(const unsigned long long*)&sB[kk * 68 + nt];
            unsigned long long b1 = *(const unsigned long long*)&sB[kk * 68 + nt + 2];
            float am[4] = { a.x, a.y, a.z, a.w };
#pragma unroll
            for (int i = 0; i < 4; i++) {
                unsigned long long ap = pk2(am[i], am[i]);
                ffma2(acc[i][0], ap, b0);
                ffma2(acc[i][1], ap, b1);
            }
        }
    }
#pragma unroll
    for (int i = 0; i < 4; i++) {
        float2 lo = unpk(acc[i][0]);
        float2 hi = unpk(acc[i][1]);
        float vals[4] = { lo.x, lo.y, hi.x, hi.y };
        int m = m0 + mt + i;
        if (m < BL) {
#pragma unroll
            for (int j = 0; j < 4; j++)
                atomicAdd(&g_out_acc[m * Dd + nt + n0 + j], vals[j]);
        }
    }
}

// ---------------------------------------------------------------------------
// K6: finalize  out[m,n] = acc[m,n] * rsqrt(sumsq[m])
// ---------------------------------------------------------------------------
__global__ void finalize_kernel(float* __restrict__ out) {
    int idx = blockIdx.x * 256 + threadIdx.x;
    if (idx < OUT_O) {
        int m = idx >> 8;
        out[idx] = g_out_acc[idx] * rsqrtf(g_sumsq[m]);
    }
}

// ---------------------------------------------------------------------------
extern "C" void kernel_launch(void* const* d_in, const int* in_sizes, int n_in,
                              void* d_out, int out_size) {
    const float* hs     = (const float*)d_in[0];   // (8,39,256,256)
    const float* conv_w = (const float*)d_in[1];   // (512,39,5,5)
    const float* conv_b = (const float*)d_in[2];   // (512,)
    const float* out_w  = (const float*)d_in[3];   // (256,63504)
    float* out = (float*)d_out;                    // [out | attention]
    float* attn = out + OUT_O;

    init_kernel<<<(OUT_O + 255) / 256, 256>>>();
    gram_kernel<<<dim3(256, Bb), 256>>>(hs);
    softmax_kernel<<<BL, 32>>>(attn);
    attnapply_kernel<<<dim3(128, Bb), 256>>>(hs, attn);
    conv_kernel<<<dim3(4, 4, BL), 256>>>(conv_w, conv_b);
    gemm_kernel<<<dim3(4, 5, 16), 256>>>(out_w);
    finalize_kernel<<<(OUT_O + 255) / 256, 256>>>(out);
}

// round 9
// speedup vs baseline: 2.1678x; 2.1678x over previous
#include <cuda_runtime.h>
#include <math.h>
#include <stdint.h>

#define Bb 8
#define Ll 39
#define Dd 256
#define DE 65536            // D*D
#define Mm 252
#define Ff 63504            // M*M
#define BL 312              // B*L
#define OUT_O 79872         // B*L*D

// ---- scratch (device globals; no allocation allowed) ----
__device__ float g_scores[BL * Ll];              // 12168
__device__ float g_sumsq[BL];                    // 312
__device__ float g_out_acc[OUT_O];               // 79872
__device__ float g_x[(size_t)Bb * Ll * DE];      // 81.8 MB  post-attention maps
__device__ float g_e[(size_t)BL * Ff];           // 79.3 MB  tril(exp(conv)) rows

// ===========================================================================
// helpers
// ===========================================================================
__device__ __forceinline__ uint32_t f2tf32(float f) {
    uint32_t r;
    asm("cvt.rna.tf32.f32 %0, %1;" : "=r"(r) : "f"(f));
    return r;
}
__device__ __forceinline__ void mma_tf32(float* d,
                                         uint32_t a0, uint32_t a1, uint32_t a2, uint32_t a3,
                                         uint32_t b0, uint32_t b1) {
    asm volatile(
        "mma.sync.aligned.m16n8k8.row.col.f32.tf32.tf32.f32 "
        "{%0,%1,%2,%3}, {%4,%5,%6,%7}, {%8,%9}, {%0,%1,%2,%3};"
        : "+f"(d[0]), "+f"(d[1]), "+f"(d[2]), "+f"(d[3])
        : "r"(a0), "r"(a1), "r"(a2), "r"(a3), "r"(b0), "r"(b1));
}

// ---------------------------------------------------------------------------
// init: zero accumulators
// ---------------------------------------------------------------------------
__global__ void init_kernel() {
    int i = blockIdx.x * 256 + threadIdx.x;
    if (i < BL * Ll) g_scores[i] = 0.f;
    if (i < BL)      g_sumsq[i] = 0.f;
    if (i < OUT_O)   g_out_acc[i] = 0.f;
}

// ---------------------------------------------------------------------------
// K1: Gram matrix  scores[b,i,j] = dot(H[b,i], H[b,j]) / 256  (Round-1 proven)
// ---------------------------------------------------------------------------
__global__ __launch_bounds__(256) void gram_kernel(const float* __restrict__ H) {
    __shared__ float sh[Ll * 257];
    int b = blockIdx.y, ch = blockIdx.x;
    int t = threadIdx.x;
    const float* Hb = H + (size_t)b * Ll * DE + ch * 256;
    for (int idx = t; idx < Ll * 256; idx += 256) {
        int i = idx >> 8, c = idx & 255;
        sh[i * 257 + c] = Hb[(size_t)i * DE + c];
    }
    __syncthreads();
    int a = t >> 4, bb = t & 15;
    float acc[3][3] = {};
    for (int k = 0; k < 256; k++) {
        float ra[3], rb[3];
#pragma unroll
        for (int p = 0; p < 3; p++) { int i = a + 16 * p; ra[p] = sh[min(i, Ll - 1) * 257 + k]; }
#pragma unroll
        for (int q = 0; q < 3; q++) { int j = bb + 16 * q; rb[q] = sh[min(j, Ll - 1) * 257 + k]; }
#pragma unroll
        for (int p = 0; p < 3; p++)
#pragma unroll
            for (int q = 0; q < 3; q++) acc[p][q] += ra[p] * rb[q];
    }
#pragma unroll
    for (int p = 0; p < 3; p++)
#pragma unroll
        for (int q = 0; q < 3; q++) {
            int i = a + 16 * p, j = bb + 16 * q;
            if (i < Ll && j < Ll)
                atomicAdd(&g_scores[(b * Ll + i) * Ll + j], acc[p][q] * (1.f / 256.f));
        }
}

// ---------------------------------------------------------------------------
// K2: softmax over j (39)  (Round-1 proven)
// ---------------------------------------------------------------------------
__global__ void softmax_kernel(float* __restrict__ attn) {
    int row = blockIdx.x;
    int lane = threadIdx.x;
    float v0 = (lane < Ll) ? g_scores[row * Ll + lane] : -1e30f;
    float v1 = (lane + 32 < Ll) ? g_scores[row * Ll + lane + 32] : -1e30f;
    float m = fmaxf(v0, v1);
#pragma unroll
    for (int off = 16; off; off >>= 1) m = fmaxf(m, __shfl_xor_sync(0xffffffffu, m, off));
    float e0 = (lane < Ll) ? expf(v0 - m) : 0.f;
    float e1 = (lane + 32 < Ll) ? expf(v1 - m) : 0.f;
    float s = e0 + e1;
#pragma unroll
    for (int off = 16; off; off >>= 1) s += __shfl_xor_sync(0xffffffffu, s, off);
    float inv = 1.f / s;
    if (lane < Ll) attn[row * Ll + lane] = e0 * inv;
    if (lane + 32 < Ll) attn[row * Ll + lane + 32] = e1 * inv;
}

// ---------------------------------------------------------------------------
// K3: attn apply (Round-1 proven: scalar fp32, 1 elem/thread)
// ---------------------------------------------------------------------------
__global__ __launch_bounds__(256) void attnapply_kernel(const float* __restrict__ H,
                                                        const float* __restrict__ attn) {
    int b = blockIdx.y;
    int pos = blockIdx.x * 256 + threadIdx.x;
    __shared__ float sA[Ll * Ll];
    for (int idx = threadIdx.x; idx < Ll * Ll; idx += 256)
        sA[idx] = attn[b * Ll * Ll + idx];
    __syncthreads();
    float acc[Ll];
#pragma unroll
    for (int i = 0; i < Ll; i++) acc[i] = 0.f;
    const float* Hb = H + (size_t)b * Ll * DE + pos;
#pragma unroll 1
    for (int j = 0; j < Ll; j++) {
        float h = Hb[(size_t)j * DE];
#pragma unroll
        for (int i = 0; i < Ll; i++) acc[i] += sA[i * Ll + j] * h;
    }
    float* xb = g_x + (size_t)b * Ll * DE + pos;
#pragma unroll
    for (int i = 0; i < Ll; i++) xb[(size_t)i * DE] = acc[i];
}

// ---------------------------------------------------------------------------
// K4: conv 5x5 via tf32 mma.sync implicit GEMM, fused epilogue.
// grid (4, 32, 8): block = 8 out rows x 64 out cols. 256 thr = 8 warps,
// warp w = output row w of tile, 4 col-strips of 16 (M), 5 n8-tiles (och 40).
// K chunk = (in-ch c, kh) with kw padded 5->8 (B zeros in pad).
// ---------------------------------------------------------------------------
__global__ __launch_bounds__(256) void conv_mma_kernel(const float* __restrict__ W,
                                                       const float* __restrict__ bias) {
    __shared__ uint32_t s_in[12 * 72];        // 12 input rows x 72 cols (tf32 bits)
    __shared__ uint32_t w_s[5 * 8 * 40];      // [kh][kw8][och40] (tf32 bits)
    __shared__ float s_sq[40];
    int t = threadIdx.x;
    int b = blockIdx.z;
    int R0 = blockIdx.y * 8;
    int C0 = blockIdx.x * 64;
    int w = t >> 5, lane = t & 31, g = lane >> 2, tg = lane & 3;
    if (t < 40) s_sq[t] = 0.f;

    float acc[4][5][4];
#pragma unroll
    for (int cs = 0; cs < 4; cs++)
#pragma unroll
        for (int nt = 0; nt < 5; nt++)
#pragma unroll
            for (int r = 0; r < 4; r++) acc[cs][nt][r] = 0.f;

    const float* xb = g_x + (size_t)b * Ll * DE;

#pragma unroll 1
    for (int c = 0; c < Ll; c++) {
        __syncthreads();
        // stage input rows R0..R0+11, cols C0..C0+71 (OOB -> 0)
        for (int idx = t; idx < 12 * 72; idx += 256) {
            int rr = idx / 72, cc = idx % 72;
            int gr = R0 + rr, gc = C0 + cc;
            float v = (gr < Dd && gc < Dd) ? xb[(size_t)c * DE + gr * Dd + gc] : 0.f;
            s_in[idx] = f2tf32(v);
        }
        // stage weights for this c: [kh][kw(8, pad>=5 zero)][o(40, pad>=39 zero)]
        for (int idx = t; idx < 1600; idx += 256) {
            int o = idx % 40;
            int kwp = (idx / 40) & 7;
            int kh = idx / 320;
            float v = (o < Ll && kwp < 5) ? W[o * 975 + c * 25 + kh * 5 + kwp] : 0.f;
            w_s[idx] = f2tf32(v);
        }
        __syncthreads();
#pragma unroll
        for (int kh = 0; kh < 5; kh++) {
            int ir = w + kh;
            uint32_t bf[5][2];
#pragma unroll
            for (int nt = 0; nt < 5; nt++) {
                bf[nt][0] = w_s[kh * 320 + tg * 40 + nt * 8 + g];
                bf[nt][1] = w_s[kh * 320 + (tg + 4) * 40 + nt * 8 + g];
            }
#pragma unroll
            for (int cs = 0; cs < 4; cs++) {
                int base = ir * 72 + cs * 16 + g + tg;
                uint32_t a0 = s_in[base];        // m=g,   k=tg
                uint32_t a1 = s_in[base + 8];    // m=g+8, k=tg
                uint32_t a2 = s_in[base + 4];    // m=g,   k=tg+4
                uint32_t a3 = s_in[base + 12];   // m=g+8, k=tg+4
#pragma unroll
                for (int nt = 0; nt < 5; nt++)
                    mma_tf32(acc[cs][nt], a0, a1, a2, a3, bf[nt][0], bf[nt][1]);
            }
        }
    }

    // epilogue: +bias, exp, sumsq (full matrix), tril store
    int R = R0 + w;
    float bs[5][2];
#pragma unroll
    for (int nt = 0; nt < 5; nt++) { bs[nt][0] = 0.f; bs[nt][1] = 0.f; }
    size_t ebase = (size_t)b * Ll;
#pragma unroll
    for (int nt = 0; nt < 5; nt++) {
        int och0 = nt * 8 + 2 * tg;
        float bv0 = (och0 < Ll) ? bias[och0] : 0.f;
        float bv1 = (och0 + 1 < Ll) ? bias[och0 + 1] : 0.f;
#pragma unroll
        for (int cs = 0; cs < 4; cs++) {
            int col0 = C0 + cs * 16 + g;
#pragma unroll
            for (int half = 0; half < 2; half++) {          // m = g or g+8
                int col = col0 + half * 8;
                float v0 = acc[cs][nt][half * 2 + 0];
                float v1 = acc[cs][nt][half * 2 + 1];
                if (R < Mm && col < Mm) {
                    if (och0 < Ll) {
                        float e = expf(v0 + bv0);
                        bs[nt][0] += e * e;
                        g_e[(ebase + och0) * Ff + (size_t)R * Mm + col] = (R >= col) ? e : 0.f;
                    }
                    if (och0 + 1 < Ll) {
                        float e = expf(v1 + bv1);
                        bs[nt][1] += e * e;
                        g_e[(ebase + och0 + 1) * Ff + (size_t)R * Mm + col] = (R >= col) ? e : 0.f;
                    }
                }
            }
        }
    }
#pragma unroll
    for (int nt = 0; nt < 5; nt++) {
        int och0 = nt * 8 + 2 * tg;
        if (och0 < Ll) atomicAdd(&s_sq[och0], bs[nt][0]);
        if (och0 + 1 < Ll) atomicAdd(&s_sq[och0 + 1], bs[nt][1]);
    }
    __syncthreads();
    if (t < Ll) atomicAdd(&g_sumsq[b * Ll + t], s_sq[t]);
}

// ---------------------------------------------------------------------------
// K5: SIMT GEMM (Round-1 proven). Out[312,256] += E @ W2^T, split-K=16.
// ---------------------------------------------------------------------------
#define KCH 3969
__global__ __launch_bounds__(256) void gemm_kernel(const float* __restrict__ W2) {
    __shared__ float sA[16 * 68];
    __shared__ float sB[16 * 68];
    int n0 = blockIdx.x * 64, m0 = blockIdx.y * 64;
    int k0 = blockIdx.z * KCH, kend = k0 + KCH;
    int t = threadIdx.x;
    int mt = 4 * (t >> 4), nt = 4 * (t & 15);
    float acc[4][4] = {};
    for (int kb = k0; kb < kend; kb += 16) {
        __syncthreads();
#pragma unroll
        for (int p = 0; p < 4; p++) {
            int idx = t + p * 256;
            int rl = idx >> 4, kl = idx & 15;
            int kk = kb + kl;
            int m = m0 + rl;
            float av = (m < BL && kk < kend) ? g_e[(size_t)m * Ff + kk] : 0.f;
            sA[kl * 68 + rl] = av;
            int n = n0 + rl;
            float bv = (kk < kend) ? W2[(size_t)n * Ff + kk] : 0.f;
            sB[kl * 68 + rl] = bv;
        }
        __syncthreads();
#pragma unroll
        for (int kk = 0; kk < 16; kk++) {
            float4 a = *(const float4*)&sA[kk * 68 + mt];
            float4 bv4 = *(const float4*)&sB[kk * 68 + nt];
            float am[4] = {a.x, a.y, a.z, a.w};
            float bn[4] = {bv4.x, bv4.y, bv4.z, bv4.w};
#pragma unroll
            for (int i = 0; i < 4; i++)
#pragma unroll
                for (int j = 0; j < 4; j++) acc[i][j] += am[i] * bn[j];
        }
    }
#pragma unroll
    for (int i = 0; i < 4; i++)
#pragma unroll
        for (int j = 0; j < 4; j++) {
            int m = m0 + mt + i, n = n0 + nt + j;
            if (m < BL) atomicAdd(&g_out_acc[m * Dd + n], acc[i][j]);
        }
}

// ---------------------------------------------------------------------------
// K6: finalize  out[m,n] = acc[m,n] * rsqrt(sumsq[m])
// ---------------------------------------------------------------------------
__global__ void finalize_kernel(float* __restrict__ out) {
    int idx = blockIdx.x * 256 + threadIdx.x;
    if (idx < OUT_O) {
        int m = idx >> 8;
        out[idx] = g_out_acc[idx] * rsqrtf(g_sumsq[m]);
    }
}

// ---------------------------------------------------------------------------
extern "C" void kernel_launch(void* const* d_in, const int* in_sizes, int n_in,
                              void* d_out, int out_size) {
    const float* hs     = (const float*)d_in[0];   // (8,39,256,256)
    const float* conv_w = (const float*)d_in[1];   // (512,39,5,5)
    const float* conv_b = (const float*)d_in[2];   // (512,)
    const float* out_w  = (const float*)d_in[3];   // (256,63504)
    float* out = (float*)d_out;                    // [out | attention]
    float* attn = out + OUT_O;

    init_kernel<<<(OUT_O + 255) / 256, 256>>>();
    gram_kernel<<<dim3(256, Bb), 256>>>(hs);
    softmax_kernel<<<BL, 32>>>(attn);
    attnapply_kernel<<<dim3(256, Bb), 256>>>(hs, attn);
    conv_mma_kernel<<<dim3(4, 32, Bb), 256>>>(conv_w, conv_b);
    gemm_kernel<<<dim3(4, 5, 16), 256>>>(out_w);
    finalize_kernel<<<(OUT_O + 255) / 256, 256>>>(out);
}